// round 2
// baseline (speedup 1.0000x reference)
#include <cuda_runtime.h>
#include <math.h>

#define N_WORD 50000
#define N_DOC  10000
#define E_WW   800000
#define E_WD   320000
#define D_H    128

// ---------------- device scratch (static allocation only) ----------------
__device__ float g_tw[(size_t)N_WORD * 512];   // word transforms: [t_ww | t_wwr | t_wd | self_w]
__device__ float g_td[(size_t)N_DOC * 256];    // doc transforms:  [t_wdr | self_d]
__device__ float g_xw[(size_t)N_WORD * 128];   // layer-1 word output
__device__ float g_xd[(size_t)N_DOC * 128];    // layer-1 doc output
__device__ float g_Bw[256 * 512];              // concatenated word weights (K<=256, N=512)
__device__ float g_Bd[256 * 256];              // concatenated doc weights  (K<=256, N=256)

// CSR per relation: 0=ww, 1=wwr, 2=wd(dst=doc), 3=wdr
__device__ int g_ptr_ww[N_WORD + 1], g_ptr_wwr[N_WORD + 1], g_ptr_wdr[N_WORD + 1];
__device__ int g_ptr_wd[N_DOC + 1];
__device__ int g_cur_ww[N_WORD + 1], g_cur_wwr[N_WORD + 1], g_cur_wdr[N_WORD + 1];
__device__ int g_cur_wd[N_DOC + 1];
__device__ int g_col_ww[E_WW], g_col_wwr[E_WW], g_col_wd[E_WD], g_col_wdr[E_WD];

__device__ __forceinline__ int* cur_of(int rel) {
    switch (rel) { case 0: return g_cur_ww; case 1: return g_cur_wwr;
                   case 2: return g_cur_wd; default: return g_cur_wdr; }
}
__device__ __forceinline__ int* ptr_of(int rel) {
    switch (rel) { case 0: return g_ptr_ww; case 1: return g_ptr_wwr;
                   case 2: return g_ptr_wd; default: return g_ptr_wdr; }
}
__device__ __forceinline__ int* col_of(int rel) {
    switch (rel) { case 0: return g_col_ww; case 1: return g_col_wwr;
                   case 2: return g_col_wd; default: return g_col_wdr; }
}

// ---------------- CSR build ----------------
__global__ void zero_cnt_kernel() {
    int i = blockIdx.x * blockDim.x + threadIdx.x;
    if (i < N_WORD + 1) { g_cur_ww[i] = 0; g_cur_wwr[i] = 0; g_cur_wdr[i] = 0; }
    if (i < N_DOC + 1)  { g_cur_wd[i] = 0; }
}

__global__ void hist_kernel(const int* __restrict__ dst, int n, int rel) {
    int* cnt = cur_of(rel);
    for (int i = blockIdx.x * blockDim.x + threadIdx.x; i < n; i += gridDim.x * blockDim.x)
        atomicAdd(&cnt[dst[i]], 1);
}

// one block per relation; exclusive scan of counts -> row_ptr, cursor
__global__ void scan_all_kernel() {
    int rel = blockIdx.x;
    int n = (rel == 2) ? N_DOC : N_WORD;
    int* cnt = cur_of(rel);
    int* ptr = ptr_of(rel);
    __shared__ int sh_warp[32];
    __shared__ int sh_carry;
    if (threadIdx.x == 0) sh_carry = 0;
    __syncthreads();
    for (int base = 0; base < n; base += 1024) {
        int i = base + (int)threadIdx.x;
        int v = (i < n) ? cnt[i] : 0;
        int lane = threadIdx.x & 31, wid = threadIdx.x >> 5;
        int x = v;
        #pragma unroll
        for (int o = 1; o < 32; o <<= 1) { int y = __shfl_up_sync(0xffffffffu, x, o); if (lane >= o) x += y; }
        if (lane == 31) sh_warp[wid] = x;
        __syncthreads();
        if (wid == 0) {
            int s = sh_warp[lane];
            #pragma unroll
            for (int o = 1; o < 32; o <<= 1) { int y = __shfl_up_sync(0xffffffffu, s, o); if (lane >= o) s += y; }
            sh_warp[lane] = s;
        }
        __syncthreads();
        int pre = (wid > 0) ? sh_warp[wid - 1] : 0;
        int incl = x + pre + sh_carry;
        if (i < n) { int excl = incl - v; ptr[i] = excl; cnt[i] = excl; }
        __syncthreads();
        if (threadIdx.x == 1023) sh_carry = incl;
        __syncthreads();
    }
    if (threadIdx.x == 0) { ptr[n] = sh_carry; cnt[n] = sh_carry; }
}

__global__ void scatter_kernel(const int* __restrict__ src, const int* __restrict__ dst,
                               int n, int rel) {
    int* cur = cur_of(rel);
    int* col = col_of(rel);
    for (int i = blockIdx.x * blockDim.x + threadIdx.x; i < n; i += gridDim.x * blockDim.x) {
        int p = atomicAdd(&cur[dst[i]], 1);
        col[p] = src[i];
    }
}

// ---------------- weight concat prep ----------------
// g_Bw[k, 0:128]=Wn[0], [128:256]=Wn[1], [256:384]=Wn[2], [384:512]=Ws[0]+Ws[1]+Ws[3]
__global__ void prep_w_kernel(const float* __restrict__ Ws, const float* __restrict__ Wn, int K) {
    int i = blockIdx.x * blockDim.x + threadIdx.x;
    if (i >= K * 128) return;
    int k = i / 128, n = i % 128;
    int KN = K * 128;
    g_Bw[k * 512 + n]       = Wn[0 * KN + k * 128 + n];
    g_Bw[k * 512 + 128 + n] = Wn[1 * KN + k * 128 + n];
    g_Bw[k * 512 + 256 + n] = Wn[2 * KN + k * 128 + n];
    g_Bw[k * 512 + 384 + n] = Ws[0 * KN + k * 128 + n] + Ws[1 * KN + k * 128 + n]
                            + Ws[3 * KN + k * 128 + n];
}
// g_Bd[k, 0:128]=Wn[3], [128:256]=Ws[2]
__global__ void prep_d_kernel(const float* __restrict__ Ws, const float* __restrict__ Wn, int K) {
    int i = blockIdx.x * blockDim.x + threadIdx.x;
    if (i >= K * 128) return;
    int k = i / 128, n = i % 128;
    int KN = K * 128;
    g_Bd[k * 256 + n]       = Wn[3 * KN + k * 128 + n];
    g_Bd[k * 256 + 128 + n] = Ws[2 * KN + k * 128 + n];
}

// ---------------- SGEMM: C[M,N] = A[M,K] @ B[K,N], row-major ----------------
#define BM 128
#define BN 128
#define BK 16
#define TM 8
#define TN 8

// a_sel: 0 -> use a_ext (input tensor); 1 -> g_xw; 2 -> g_xd
// b_sel: 0 -> g_Bw; 1 -> g_Bd.   c_sel: 0 -> g_tw; 1 -> g_td
__global__ __launch_bounds__(256) void sgemm_kernel(const float* __restrict__ a_ext,
                                                    int a_sel, int b_sel, int c_sel,
                                                    int M, int K, int N) {
    const float* A = (a_sel == 0) ? a_ext : (a_sel == 1 ? (const float*)g_xw : (const float*)g_xd);
    const float* B = (b_sel == 0) ? (const float*)g_Bw : (const float*)g_Bd;
    float* C = (c_sel == 0) ? g_tw : g_td;

    __shared__ float As[BK][BM + 4];
    __shared__ float Bs[BK][BN];

    int tid = threadIdx.x;
    int tn = tid % 16, tm = tid / 16;
    int row0 = blockIdx.y * BM, col0 = blockIdx.x * BN;

    float acc[TM][TN] = {{0.0f}};

    int arow = tid / 4;          // 0..63
    int acol = (tid % 4) * 4;    // 0,4,8,12
    int brow = tid / 32;         // 0..7
    int bcol = (tid % 32) * 4;   // 0..124

    for (int k0 = 0; k0 < K; k0 += BK) {
        #pragma unroll
        for (int h = 0; h < 2; ++h) {
            int r = arow + h * 64;
            int gr = row0 + r;
            float4 v = make_float4(0.f, 0.f, 0.f, 0.f);
            if (gr < M) v = *reinterpret_cast<const float4*>(A + (size_t)gr * K + k0 + acol);
            As[acol + 0][r] = v.x; As[acol + 1][r] = v.y;
            As[acol + 2][r] = v.z; As[acol + 3][r] = v.w;
        }
        #pragma unroll
        for (int h = 0; h < 2; ++h) {
            int r = brow + h * 8;
            float4 v = *reinterpret_cast<const float4*>(B + (size_t)(k0 + r) * N + col0 + bcol);
            *reinterpret_cast<float4*>(&Bs[r][bcol]) = v;
        }
        __syncthreads();
        #pragma unroll
        for (int k = 0; k < BK; ++k) {
            float ra[TM], rb[TN];
            #pragma unroll
            for (int i = 0; i < TM; ++i) ra[i] = As[k][tm * TM + i];
            #pragma unroll
            for (int j = 0; j < TN; ++j) rb[j] = Bs[k][tn * TN + j];
            #pragma unroll
            for (int i = 0; i < TM; ++i)
                #pragma unroll
                for (int j = 0; j < TN; ++j)
                    acc[i][j] += ra[i] * rb[j];
        }
        __syncthreads();
    }

    #pragma unroll
    for (int i = 0; i < TM; ++i) {
        int gr = row0 + tm * TM + i;
        if (gr >= M) continue;
        #pragma unroll
        for (int j = 0; j < TN; j += 4) {
            *reinterpret_cast<float4*>(C + (size_t)gr * N + col0 + tn * TN + j) =
                make_float4(acc[i][j], acc[i][j + 1], acc[i][j + 2], acc[i][j + 3]);
        }
    }
}

// ---------------- aggregation + combine ----------------
__device__ __forceinline__ float4 gather_mean(const float* __restrict__ t, int stride, int base,
                                              const int* __restrict__ ptr,
                                              const int* __restrict__ col, int v, int c4) {
    int beg = ptr[v], end = ptr[v + 1];
    float4 acc = make_float4(0.f, 0.f, 0.f, 0.f);
    for (int e = beg; e < end; ++e) {
        int s = col[e];
        float4 val = *reinterpret_cast<const float4*>(t + (size_t)s * stride + base + c4);
        acc.x += val.x; acc.y += val.y; acc.z += val.z; acc.w += val.w;
    }
    int d = end - beg;
    float inv = 1.0f / (float)(d > 0 ? d : 1);
    acc.x *= inv; acc.y *= inv; acc.z *= inv; acc.w *= inv;
    return acc;
}

template <bool FINAL>
__global__ void combine_word_kernel(const float* __restrict__ b,
                                    const float* __restrict__ lin_w,
                                    const float* __restrict__ lin_b,
                                    float* __restrict__ out) {
    int warp = (blockIdx.x * blockDim.x + threadIdx.x) >> 5;
    if (warp >= N_WORD) return;
    int lane = threadIdx.x & 31;
    int c4 = lane * 4;
    int v = warp;

    float4 h = *reinterpret_cast<const float4*>(g_tw + (size_t)v * 512 + 384 + c4); // self
    float4 m0 = gather_mean(g_tw, 512, 0,   g_ptr_ww,  g_col_ww,  v, c4);
    float4 m1 = gather_mean(g_tw, 512, 128, g_ptr_wwr, g_col_wwr, v, c4);
    float4 m3 = gather_mean(g_td, 256, 0,   g_ptr_wdr, g_col_wdr, v, c4);

    h.x = fmaxf(h.x + m0.x + m1.x + m3.x + b[c4 + 0] + b[128 + c4 + 0] + b[384 + c4 + 0], 0.f);
    h.y = fmaxf(h.y + m0.y + m1.y + m3.y + b[c4 + 1] + b[128 + c4 + 1] + b[384 + c4 + 1], 0.f);
    h.z = fmaxf(h.z + m0.z + m1.z + m3.z + b[c4 + 2] + b[128 + c4 + 2] + b[384 + c4 + 2], 0.f);
    h.w = fmaxf(h.w + m0.w + m1.w + m3.w + b[c4 + 3] + b[128 + c4 + 3] + b[384 + c4 + 3], 0.f);

    if (!FINAL) {
        *reinterpret_cast<float4*>(g_xw + (size_t)v * 128 + c4) = h;
    } else {
        float4 lw = *reinterpret_cast<const float4*>(lin_w + c4);
        float p = h.x * lw.x + h.y * lw.y + h.z * lw.z + h.w * lw.w;
        #pragma unroll
        for (int o = 16; o > 0; o >>= 1) p += __shfl_down_sync(0xffffffffu, p, o);
        if (lane == 0) out[v] = 1.0f / (1.0f + expf(-(p + lin_b[0])));
    }
}

template <bool FINAL>
__global__ void combine_doc_kernel(const float* __restrict__ b,
                                   const float* __restrict__ lin_w,
                                   const float* __restrict__ lin_b,
                                   float* __restrict__ out) {
    int warp = (blockIdx.x * blockDim.x + threadIdx.x) >> 5;
    if (warp >= N_DOC) return;
    int lane = threadIdx.x & 31;
    int c4 = lane * 4;
    int v = warp;

    float4 h = *reinterpret_cast<const float4*>(g_td + (size_t)v * 256 + 128 + c4); // self
    float4 m2 = gather_mean(g_tw, 512, 256, g_ptr_wd, g_col_wd, v, c4);

    h.x = fmaxf(h.x + m2.x + b[256 + c4 + 0], 0.f);
    h.y = fmaxf(h.y + m2.y + b[256 + c4 + 1], 0.f);
    h.z = fmaxf(h.z + m2.z + b[256 + c4 + 2], 0.f);
    h.w = fmaxf(h.w + m2.w + b[256 + c4 + 3], 0.f);

    if (!FINAL) {
        *reinterpret_cast<float4*>(g_xd + (size_t)v * 128 + c4) = h;
    } else {
        float4 lw = *reinterpret_cast<const float4*>(lin_w + c4);
        float p = h.x * lw.x + h.y * lw.y + h.z * lw.z + h.w * lw.w;
        #pragma unroll
        for (int o = 16; o > 0; o >>= 1) p += __shfl_down_sync(0xffffffffu, p, o);
        if (lane == 0) out[N_WORD + v] = 1.0f / (1.0f + expf(-(p + lin_b[0])));
    }
}

// ---------------- host launch ----------------
extern "C" void kernel_launch(void* const* d_in, const int* in_sizes, int n_in,
                              void* d_out, int out_size) {
    const float* x_word  = (const float*)d_in[0];
    const float* x_doc   = (const float*)d_in[1];
    const int*   ww_src  = (const int*)d_in[2];
    const int*   ww_dst  = (const int*)d_in[3];
    const int*   wwr_src = (const int*)d_in[4];
    const int*   wwr_dst = (const int*)d_in[5];
    const int*   wd_src  = (const int*)d_in[6];
    const int*   wd_dst  = (const int*)d_in[7];
    const int*   wdr_src = (const int*)d_in[8];
    const int*   wdr_dst = (const int*)d_in[9];
    const float* Wself1  = (const float*)d_in[10];
    const float* Wneigh1 = (const float*)d_in[11];
    const float* b1      = (const float*)d_in[12];
    const float* Wself2  = (const float*)d_in[13];
    const float* Wneigh2 = (const float*)d_in[14];
    const float* b2      = (const float*)d_in[15];
    const float* lin_w   = (const float*)d_in[16];
    const float* lin_b   = (const float*)d_in[17];
    float* out = (float*)d_out;

    // --- CSR build (int atomics only) ---
    zero_cnt_kernel<<<(N_WORD + 256) / 256, 256>>>();
    hist_kernel<<<512, 256>>>(ww_dst,  E_WW, 0);
    hist_kernel<<<512, 256>>>(wwr_dst, E_WW, 1);
    hist_kernel<<<512, 256>>>(wd_dst,  E_WD, 2);
    hist_kernel<<<512, 256>>>(wdr_dst, E_WD, 3);
    scan_all_kernel<<<4, 1024>>>();
    scatter_kernel<<<512, 256>>>(ww_src,  ww_dst,  E_WW, 0);
    scatter_kernel<<<512, 256>>>(wwr_src, wwr_dst, E_WW, 1);
    scatter_kernel<<<512, 256>>>(wd_src,  wd_dst,  E_WD, 2);
    scatter_kernel<<<512, 256>>>(wdr_src, wdr_dst, E_WD, 3);

    // --- layer 1 (K = 256) ---
    prep_w_kernel<<<(256 * 128 + 255) / 256, 256>>>(Wself1, Wneigh1, 256);
    prep_d_kernel<<<(256 * 128 + 255) / 256, 256>>>(Wself1, Wneigh1, 256);
    sgemm_kernel<<<dim3(512 / BN, (N_WORD + BM - 1) / BM), 256>>>(x_word, 0, 0, 0, N_WORD, 256, 512);
    sgemm_kernel<<<dim3(256 / BN, (N_DOC + BM - 1) / BM), 256>>>(x_doc, 0, 1, 1, N_DOC, 256, 256);
    combine_word_kernel<false><<<(N_WORD + 7) / 8, 256>>>(b1, lin_w, lin_b, out);
    combine_doc_kernel<false><<<(N_DOC + 7) / 8, 256>>>(b1, lin_w, lin_b, out);

    // --- layer 2 (K = 128) + fused final linear/sigmoid ---
    prep_w_kernel<<<(128 * 128 + 255) / 256, 256>>>(Wself2, Wneigh2, 128);
    prep_d_kernel<<<(128 * 128 + 255) / 256, 256>>>(Wself2, Wneigh2, 128);
    sgemm_kernel<<<dim3(512 / BN, (N_WORD + BM - 1) / BM), 256>>>(nullptr, 1, 0, 0, N_WORD, 128, 512);
    sgemm_kernel<<<dim3(256 / BN, (N_DOC + BM - 1) / BM), 256>>>(nullptr, 2, 1, 1, N_DOC, 128, 256);
    combine_word_kernel<true><<<(N_WORD + 7) / 8, 256>>>(b2, lin_w, lin_b, out);
    combine_doc_kernel<true><<<(N_DOC + 7) / 8, 256>>>(b2, lin_w, lin_b, out);
}

// round 3
// speedup vs baseline: 1.4804x; 1.4804x over previous
#include <cuda_runtime.h>
#include <math.h>
#include <stdint.h>

#define N_WORD 50000
#define N_DOC  10000
#define E_WW   800000
#define E_WD   320000

// ---------------- device scratch (static allocation only) ----------------
__device__ float g_tw[(size_t)N_WORD * 512];   // word transforms: [t_ww | t_wwr | t_wd | self_w]
__device__ float g_td[(size_t)N_DOC * 256];    // doc transforms:  [t_wdr | self_d]
__device__ float g_xw[(size_t)N_WORD * 128];   // layer-1 word output
__device__ float g_xd[(size_t)N_DOC * 128];    // layer-1 doc output
__device__ float g_Bw[256 * 512];              // concatenated word weights (K<=256, N=512)
__device__ float g_Bd[256 * 256];              // concatenated doc weights  (K<=256, N=256)

// CSR per relation: 0=ww, 1=wwr, 2=wd(dst=doc), 3=wdr
__device__ int g_ptr_ww[N_WORD + 1], g_ptr_wwr[N_WORD + 1], g_ptr_wdr[N_WORD + 1];
__device__ int g_ptr_wd[N_DOC + 1];
__device__ int g_cur_ww[N_WORD + 1], g_cur_wwr[N_WORD + 1], g_cur_wdr[N_WORD + 1];
__device__ int g_cur_wd[N_DOC + 1];
__device__ int g_col_ww[E_WW], g_col_wwr[E_WW], g_col_wd[E_WD], g_col_wdr[E_WD];

__device__ __forceinline__ int* cur_of(int rel) {
    switch (rel) { case 0: return g_cur_ww; case 1: return g_cur_wwr;
                   case 2: return g_cur_wd; default: return g_cur_wdr; }
}
__device__ __forceinline__ int* ptr_of(int rel) {
    switch (rel) { case 0: return g_ptr_ww; case 1: return g_ptr_wwr;
                   case 2: return g_ptr_wd; default: return g_ptr_wdr; }
}
__device__ __forceinline__ int* col_of(int rel) {
    switch (rel) { case 0: return g_col_ww; case 1: return g_col_wwr;
                   case 2: return g_col_wd; default: return g_col_wdr; }
}

// ---------------- CSR build ----------------
__global__ void zero_cnt_kernel() {
    int i = blockIdx.x * blockDim.x + threadIdx.x;
    if (i < N_WORD + 1) { g_cur_ww[i] = 0; g_cur_wwr[i] = 0; g_cur_wdr[i] = 0; }
    if (i < N_DOC + 1)  { g_cur_wd[i] = 0; }
}

__global__ void hist_kernel(const int* __restrict__ dst, int n, int rel) {
    int* cnt = cur_of(rel);
    for (int i = blockIdx.x * blockDim.x + threadIdx.x; i < n; i += gridDim.x * blockDim.x)
        atomicAdd(&cnt[dst[i]], 1);
}

// one block per relation; exclusive scan of counts -> row_ptr, cursor
__global__ void scan_all_kernel() {
    int rel = blockIdx.x;
    int n = (rel == 2) ? N_DOC : N_WORD;
    int* cnt = cur_of(rel);
    int* ptr = ptr_of(rel);
    __shared__ int sh_warp[32];
    __shared__ int sh_carry;
    if (threadIdx.x == 0) sh_carry = 0;
    __syncthreads();
    for (int base = 0; base < n; base += 1024) {
        int i = base + (int)threadIdx.x;
        int v = (i < n) ? cnt[i] : 0;
        int lane = threadIdx.x & 31, wid = threadIdx.x >> 5;
        int x = v;
        #pragma unroll
        for (int o = 1; o < 32; o <<= 1) { int y = __shfl_up_sync(0xffffffffu, x, o); if (lane >= o) x += y; }
        if (lane == 31) sh_warp[wid] = x;
        __syncthreads();
        if (wid == 0) {
            int s = sh_warp[lane];
            #pragma unroll
            for (int o = 1; o < 32; o <<= 1) { int y = __shfl_up_sync(0xffffffffu, s, o); if (lane >= o) s += y; }
            sh_warp[lane] = s;
        }
        __syncthreads();
        int pre = (wid > 0) ? sh_warp[wid - 1] : 0;
        int incl = x + pre + sh_carry;
        if (i < n) { int excl = incl - v; ptr[i] = excl; cnt[i] = excl; }
        __syncthreads();
        if (threadIdx.x == 1023) sh_carry = incl;
        __syncthreads();
    }
    if (threadIdx.x == 0) { ptr[n] = sh_carry; cnt[n] = sh_carry; }
}

__global__ void scatter_kernel(const int* __restrict__ src, const int* __restrict__ dst,
                               int n, int rel) {
    int* cur = cur_of(rel);
    int* col = col_of(rel);
    for (int i = blockIdx.x * blockDim.x + threadIdx.x; i < n; i += gridDim.x * blockDim.x) {
        int p = atomicAdd(&cur[dst[i]], 1);
        col[p] = src[i];
    }
}

// ---------------- weight concat prep ----------------
__global__ void prep_w_kernel(const float* __restrict__ Ws, const float* __restrict__ Wn, int K) {
    int i = blockIdx.x * blockDim.x + threadIdx.x;
    if (i >= K * 128) return;
    int k = i / 128, n = i % 128;
    int KN = K * 128;
    g_Bw[k * 512 + n]       = Wn[0 * KN + k * 128 + n];
    g_Bw[k * 512 + 128 + n] = Wn[1 * KN + k * 128 + n];
    g_Bw[k * 512 + 256 + n] = Wn[2 * KN + k * 128 + n];
    g_Bw[k * 512 + 384 + n] = Ws[0 * KN + k * 128 + n] + Ws[1 * KN + k * 128 + n]
                            + Ws[3 * KN + k * 128 + n];
}
__global__ void prep_d_kernel(const float* __restrict__ Ws, const float* __restrict__ Wn, int K) {
    int i = blockIdx.x * blockDim.x + threadIdx.x;
    if (i >= K * 128) return;
    int k = i / 128, n = i % 128;
    int KN = K * 128;
    g_Bd[k * 256 + n]       = Wn[3 * KN + k * 128 + n];
    g_Bd[k * 256 + 128 + n] = Ws[2 * KN + k * 128 + n];
}

// ---------------- tf32 tensor-core GEMM: C[M,N] = A[M,K] @ B[K,N] ----------------
// Block tile 128x128, BK=16, 256 threads = 8 warps in 2(m) x 4(n); warp tile 64x32.
#define BM 128
#define BN 128
#define BK 16
#define SMP 132   // padded stride (bank-conflict-free fragment loads)

__device__ __forceinline__ uint32_t f2tf32(float f) {
    uint32_t u;
    asm("cvt.rna.tf32.f32 %0, %1;" : "=r"(u) : "f"(f));
    return u;
}

__global__ __launch_bounds__(256) void gemm_tf32_kernel(const float* __restrict__ a_ext,
                                                        int a_sel, int b_sel, int c_sel,
                                                        int M, int K, int N) {
    const float* A = (a_sel == 0) ? a_ext : (a_sel == 1 ? (const float*)g_xw : (const float*)g_xd);
    const float* B = (b_sel == 0) ? (const float*)g_Bw : (const float*)g_Bd;
    float* C = (c_sel == 0) ? g_tw : g_td;

    __shared__ uint32_t As[BK][SMP];   // [k][m]
    __shared__ uint32_t Bs[BK][SMP];   // [k][n]

    const int tid = threadIdx.x;
    const int warp = tid >> 5, lane = tid & 31;
    const int g = lane >> 2, t = lane & 3;
    const int wm0 = (warp & 1) * 64;
    const int wn0 = (warp >> 1) * 32;
    const int row0 = blockIdx.y * BM, col0 = blockIdx.x * BN;

    float c[4][4][4];
    #pragma unroll
    for (int i = 0; i < 4; ++i)
        #pragma unroll
        for (int j = 0; j < 4; ++j)
            #pragma unroll
            for (int r = 0; r < 4; ++r) c[i][j][r] = 0.0f;

    const int ar = tid >> 2;             // 0..63
    const int ak = (tid & 3) * 4;        // 0,4,8,12
    const int br = tid >> 5;             // 0..7
    const int bc = (tid & 31) * 4;       // 0..124

    for (int k0 = 0; k0 < K; k0 += BK) {
        // stage A (convert to tf32), layout As[k][m]
        #pragma unroll
        for (int h = 0; h < 2; ++h) {
            int r = ar + h * 64;
            int gr = row0 + r;
            float4 v = make_float4(0.f, 0.f, 0.f, 0.f);
            if (gr < M) v = *reinterpret_cast<const float4*>(A + (size_t)gr * K + k0 + ak);
            As[ak + 0][r] = f2tf32(v.x);
            As[ak + 1][r] = f2tf32(v.y);
            As[ak + 2][r] = f2tf32(v.z);
            As[ak + 3][r] = f2tf32(v.w);
        }
        // stage B (convert), layout Bs[k][n]
        #pragma unroll
        for (int h = 0; h < 2; ++h) {
            int r = br + h * 8;
            float4 v = *reinterpret_cast<const float4*>(B + (size_t)(k0 + r) * N + col0 + bc);
            uint4 u;
            u.x = f2tf32(v.x); u.y = f2tf32(v.y); u.z = f2tf32(v.z); u.w = f2tf32(v.w);
            *reinterpret_cast<uint4*>(&Bs[r][bc]) = u;
        }
        __syncthreads();

        #pragma unroll
        for (int kk = 0; kk < BK; kk += 8) {
            uint32_t af[4][4], bf[4][2];
            #pragma unroll
            for (int i = 0; i < 4; ++i) {
                int r = wm0 + i * 16 + g;
                af[i][0] = As[kk + t][r];
                af[i][1] = As[kk + t][r + 8];
                af[i][2] = As[kk + t + 4][r];
                af[i][3] = As[kk + t + 4][r + 8];
            }
            #pragma unroll
            for (int j = 0; j < 4; ++j) {
                int cc = wn0 + j * 8 + g;
                bf[j][0] = Bs[kk + t][cc];
                bf[j][1] = Bs[kk + t + 4][cc];
            }
            #pragma unroll
            for (int i = 0; i < 4; ++i)
                #pragma unroll
                for (int j = 0; j < 4; ++j) {
                    asm volatile(
                        "mma.sync.aligned.m16n8k8.row.col.f32.tf32.tf32.f32 "
                        "{%0,%1,%2,%3}, {%4,%5,%6,%7}, {%8,%9}, {%0,%1,%2,%3};"
                        : "+f"(c[i][j][0]), "+f"(c[i][j][1]), "+f"(c[i][j][2]), "+f"(c[i][j][3])
                        : "r"(af[i][0]), "r"(af[i][1]), "r"(af[i][2]), "r"(af[i][3]),
                          "r"(bf[j][0]), "r"(bf[j][1]));
                }
        }
        __syncthreads();
    }

    // epilogue
    #pragma unroll
    for (int i = 0; i < 4; ++i) {
        int r0 = row0 + wm0 + i * 16 + g;
        #pragma unroll
        for (int j = 0; j < 4; ++j) {
            int cc = col0 + wn0 + j * 8 + 2 * t;
            if (r0 < M)
                *reinterpret_cast<float2*>(C + (size_t)r0 * N + cc) =
                    make_float2(c[i][j][0], c[i][j][1]);
            if (r0 + 8 < M)
                *reinterpret_cast<float2*>(C + (size_t)(r0 + 8) * N + cc) =
                    make_float2(c[i][j][2], c[i][j][3]);
        }
    }
}

// ---------------- aggregation + combine ----------------
__device__ __forceinline__ float4 gather_mean(const float* __restrict__ t, int stride, int base,
                                              const int* __restrict__ ptr,
                                              const int* __restrict__ col, int v, int c4) {
    int beg = ptr[v], end = ptr[v + 1];
    float4 acc = make_float4(0.f, 0.f, 0.f, 0.f);
    for (int e = beg; e < end; ++e) {
        int s = col[e];
        float4 val = *reinterpret_cast<const float4*>(t + (size_t)s * stride + base + c4);
        acc.x += val.x; acc.y += val.y; acc.z += val.z; acc.w += val.w;
    }
    int d = end - beg;
    float inv = 1.0f / (float)(d > 0 ? d : 1);
    acc.x *= inv; acc.y *= inv; acc.z *= inv; acc.w *= inv;
    return acc;
}

template <bool FINAL>
__global__ void combine_word_kernel(const float* __restrict__ b,
                                    const float* __restrict__ lin_w,
                                    const float* __restrict__ lin_b,
                                    float* __restrict__ out) {
    int warp = (blockIdx.x * blockDim.x + threadIdx.x) >> 5;
    if (warp >= N_WORD) return;
    int lane = threadIdx.x & 31;
    int c4 = lane * 4;
    int v = warp;

    float4 h = *reinterpret_cast<const float4*>(g_tw + (size_t)v * 512 + 384 + c4); // self
    float4 m0 = gather_mean(g_tw, 512, 0,   g_ptr_ww,  g_col_ww,  v, c4);
    float4 m1 = gather_mean(g_tw, 512, 128, g_ptr_wwr, g_col_wwr, v, c4);
    float4 m3 = gather_mean(g_td, 256, 0,   g_ptr_wdr, g_col_wdr, v, c4);

    h.x = fmaxf(h.x + m0.x + m1.x + m3.x + b[c4 + 0] + b[128 + c4 + 0] + b[384 + c4 + 0], 0.f);
    h.y = fmaxf(h.y + m0.y + m1.y + m3.y + b[c4 + 1] + b[128 + c4 + 1] + b[384 + c4 + 1], 0.f);
    h.z = fmaxf(h.z + m0.z + m1.z + m3.z + b[c4 + 2] + b[128 + c4 + 2] + b[384 + c4 + 2], 0.f);
    h.w = fmaxf(h.w + m0.w + m1.w + m3.w + b[c4 + 3] + b[128 + c4 + 3] + b[384 + c4 + 3], 0.f);

    if (!FINAL) {
        *reinterpret_cast<float4*>(g_xw + (size_t)v * 128 + c4) = h;
    } else {
        float4 lw = *reinterpret_cast<const float4*>(lin_w + c4);
        float p = h.x * lw.x + h.y * lw.y + h.z * lw.z + h.w * lw.w;
        #pragma unroll
        for (int o = 16; o > 0; o >>= 1) p += __shfl_down_sync(0xffffffffu, p, o);
        if (lane == 0) out[v] = 1.0f / (1.0f + expf(-(p + lin_b[0])));
    }
}

template <bool FINAL>
__global__ void combine_doc_kernel(const float* __restrict__ b,
                                   const float* __restrict__ lin_w,
                                   const float* __restrict__ lin_b,
                                   float* __restrict__ out) {
    int warp = (blockIdx.x * blockDim.x + threadIdx.x) >> 5;
    if (warp >= N_DOC) return;
    int lane = threadIdx.x & 31;
    int c4 = lane * 4;
    int v = warp;

    float4 h = *reinterpret_cast<const float4*>(g_td + (size_t)v * 256 + 128 + c4); // self
    float4 m2 = gather_mean(g_tw, 512, 256, g_ptr_wd, g_col_wd, v, c4);

    h.x = fmaxf(h.x + m2.x + b[256 + c4 + 0], 0.f);
    h.y = fmaxf(h.y + m2.y + b[256 + c4 + 1], 0.f);
    h.z = fmaxf(h.z + m2.z + b[256 + c4 + 2], 0.f);
    h.w = fmaxf(h.w + m2.w + b[256 + c4 + 3], 0.f);

    if (!FINAL) {
        *reinterpret_cast<float4*>(g_xd + (size_t)v * 128 + c4) = h;
    } else {
        float4 lw = *reinterpret_cast<const float4*>(lin_w + c4);
        float p = h.x * lw.x + h.y * lw.y + h.z * lw.z + h.w * lw.w;
        #pragma unroll
        for (int o = 16; o > 0; o >>= 1) p += __shfl_down_sync(0xffffffffu, p, o);
        if (lane == 0) out[N_WORD + v] = 1.0f / (1.0f + expf(-(p + lin_b[0])));
    }
}

// ---------------- host launch ----------------
extern "C" void kernel_launch(void* const* d_in, const int* in_sizes, int n_in,
                              void* d_out, int out_size) {
    const float* x_word  = (const float*)d_in[0];
    const float* x_doc   = (const float*)d_in[1];
    const int*   ww_src  = (const int*)d_in[2];
    const int*   ww_dst  = (const int*)d_in[3];
    const int*   wwr_src = (const int*)d_in[4];
    const int*   wwr_dst = (const int*)d_in[5];
    const int*   wd_src  = (const int*)d_in[6];
    const int*   wd_dst  = (const int*)d_in[7];
    const int*   wdr_src = (const int*)d_in[8];
    const int*   wdr_dst = (const int*)d_in[9];
    const float* Wself1  = (const float*)d_in[10];
    const float* Wneigh1 = (const float*)d_in[11];
    const float* b1      = (const float*)d_in[12];
    const float* Wself2  = (const float*)d_in[13];
    const float* Wneigh2 = (const float*)d_in[14];
    const float* b2      = (const float*)d_in[15];
    const float* lin_w   = (const float*)d_in[16];
    const float* lin_b   = (const float*)d_in[17];
    float* out = (float*)d_out;

    // --- CSR build (int atomics only) ---
    zero_cnt_kernel<<<(N_WORD + 256) / 256, 256>>>();
    hist_kernel<<<512, 256>>>(ww_dst,  E_WW, 0);
    hist_kernel<<<512, 256>>>(wwr_dst, E_WW, 1);
    hist_kernel<<<512, 256>>>(wd_dst,  E_WD, 2);
    hist_kernel<<<512, 256>>>(wdr_dst, E_WD, 3);
    scan_all_kernel<<<4, 1024>>>();
    scatter_kernel<<<512, 256>>>(ww_src,  ww_dst,  E_WW, 0);
    scatter_kernel<<<512, 256>>>(wwr_src, wwr_dst, E_WW, 1);
    scatter_kernel<<<512, 256>>>(wd_src,  wd_dst,  E_WD, 2);
    scatter_kernel<<<512, 256>>>(wdr_src, wdr_dst, E_WD, 3);

    // --- layer 1 (K = 256) ---
    prep_w_kernel<<<(256 * 128 + 255) / 256, 256>>>(Wself1, Wneigh1, 256);
    prep_d_kernel<<<(256 * 128 + 255) / 256, 256>>>(Wself1, Wneigh1, 256);
    gemm_tf32_kernel<<<dim3(512 / BN, (N_WORD + BM - 1) / BM), 256>>>(x_word, 0, 0, 0, N_WORD, 256, 512);
    gemm_tf32_kernel<<<dim3(256 / BN, (N_DOC + BM - 1) / BM), 256>>>(x_doc, 0, 1, 1, N_DOC, 256, 256);
    combine_word_kernel<false><<<(N_WORD + 7) / 8, 256>>>(b1, lin_w, lin_b, out);
    combine_doc_kernel<false><<<(N_DOC + 7) / 8, 256>>>(b1, lin_w, lin_b, out);

    // --- layer 2 (K = 128) + fused final linear/sigmoid ---
    prep_w_kernel<<<(128 * 128 + 255) / 256, 256>>>(Wself2, Wneigh2, 128);
    prep_d_kernel<<<(128 * 128 + 255) / 256, 256>>>(Wself2, Wneigh2, 128);
    gemm_tf32_kernel<<<dim3(512 / BN, (N_WORD + BM - 1) / BM), 256>>>(nullptr, 1, 0, 0, N_WORD, 128, 512);
    gemm_tf32_kernel<<<dim3(256 / BN, (N_DOC + BM - 1) / BM), 256>>>(nullptr, 2, 1, 1, N_DOC, 128, 256);
    combine_word_kernel<true><<<(N_WORD + 7) / 8, 256>>>(b2, lin_w, lin_b, out);
    combine_doc_kernel<true><<<(N_DOC + 7) / 8, 256>>>(b2, lin_w, lin_b, out);
}

// round 5
// speedup vs baseline: 1.6094x; 1.0871x over previous
#include <cuda_runtime.h>
#include <cuda_fp16.h>
#include <math.h>
#include <stdint.h>

#define N_WORD 50000
#define N_DOC  10000
#define E_WW   800000
#define E_WD   320000

// ---------------- device scratch (static allocation only) ----------------
// Neighbor-transform segments stored fp16 (gathered many times), self fp32.
__device__ __half g_twn[(size_t)N_WORD * 384];  // [t_ww | t_wwr | t_wd] per word
__device__ float  g_tws[(size_t)N_WORD * 128];  // combined self transform (word)
__device__ __half g_tdn[(size_t)N_DOC * 128];   // t_wdr per doc
__device__ float  g_tds[(size_t)N_DOC * 128];   // self transform (doc)
__device__ float  g_xw[(size_t)N_WORD * 128];   // layer-1 word output
__device__ float  g_xd[(size_t)N_DOC * 128];    // layer-1 doc output
__device__ float  g_Bw[256 * 512];              // concat word weights (K<=256, N=512)
__device__ float  g_Bd[256 * 256];              // concat doc weights  (K<=256, N=256)

// CSR per relation: 0=ww, 1=wwr, 2=wd(dst=doc), 3=wdr
__device__ int g_ptr_ww[N_WORD + 1], g_ptr_wwr[N_WORD + 1], g_ptr_wdr[N_WORD + 1];
__device__ int g_ptr_wd[N_DOC + 1];
__device__ int g_cur_ww[N_WORD + 1], g_cur_wwr[N_WORD + 1], g_cur_wdr[N_WORD + 1];
__device__ int g_cur_wd[N_DOC + 1];
__device__ int g_col_ww[E_WW], g_col_wwr[E_WW], g_col_wd[E_WD], g_col_wdr[E_WD];

__device__ __forceinline__ int* cur_of(int rel) {
    switch (rel) { case 0: return g_cur_ww; case 1: return g_cur_wwr;
                   case 2: return g_cur_wd; default: return g_cur_wdr; }
}
__device__ __forceinline__ int* ptr_of(int rel) {
    switch (rel) { case 0: return g_ptr_ww; case 1: return g_ptr_wwr;
                   case 2: return g_ptr_wd; default: return g_ptr_wdr; }
}

// ---------------- CSR build ----------------
__global__ void zero_cnt_kernel() {
    int i = blockIdx.x * blockDim.x + threadIdx.x;
    if (i < N_WORD + 1) { g_cur_ww[i] = 0; g_cur_wwr[i] = 0; g_cur_wdr[i] = 0; }
    if (i < N_DOC + 1)  { g_cur_wd[i] = 0; }
}

// one launch covers all 4 relations
__global__ void hist_all_kernel(const int* __restrict__ ww_dst, const int* __restrict__ wwr_dst,
                                const int* __restrict__ wd_dst, const int* __restrict__ wdr_dst) {
    const int total = 2 * E_WW + 2 * E_WD;
    for (int i = blockIdx.x * blockDim.x + threadIdx.x; i < total; i += gridDim.x * blockDim.x) {
        if (i < E_WW)                  atomicAdd(&g_cur_ww[ww_dst[i]], 1);
        else if (i < 2 * E_WW)         atomicAdd(&g_cur_wwr[wwr_dst[i - E_WW]], 1);
        else if (i < 2 * E_WW + E_WD)  atomicAdd(&g_cur_wd[wd_dst[i - 2 * E_WW]], 1);
        else                           atomicAdd(&g_cur_wdr[wdr_dst[i - 2 * E_WW - E_WD]], 1);
    }
}

// one block per relation; exclusive scan of counts -> row_ptr, cursor
__global__ void scan_all_kernel() {
    int rel = blockIdx.x;
    int n = (rel == 2) ? N_DOC : N_WORD;
    int* cnt = cur_of(rel);
    int* ptr = ptr_of(rel);
    __shared__ int sh_warp[32];
    __shared__ int sh_carry;
    if (threadIdx.x == 0) sh_carry = 0;
    __syncthreads();
    for (int base = 0; base < n; base += 1024) {
        int i = base + (int)threadIdx.x;
        int v = (i < n) ? cnt[i] : 0;
        int lane = threadIdx.x & 31, wid = threadIdx.x >> 5;
        int x = v;
        #pragma unroll
        for (int o = 1; o < 32; o <<= 1) { int y = __shfl_up_sync(0xffffffffu, x, o); if (lane >= o) x += y; }
        if (lane == 31) sh_warp[wid] = x;
        __syncthreads();
        if (wid == 0) {
            int s = sh_warp[lane];
            #pragma unroll
            for (int o = 1; o < 32; o <<= 1) { int y = __shfl_up_sync(0xffffffffu, s, o); if (lane >= o) s += y; }
            sh_warp[lane] = s;
        }
        __syncthreads();
        int pre = (wid > 0) ? sh_warp[wid - 1] : 0;
        int incl = x + pre + sh_carry;
        if (i < n) { int excl = incl - v; ptr[i] = excl; cnt[i] = excl; }
        __syncthreads();
        if (threadIdx.x == 1023) sh_carry = incl;
        __syncthreads();
    }
    if (threadIdx.x == 0) { ptr[n] = sh_carry; cnt[n] = sh_carry; }
}

__global__ void scatter_all_kernel(const int* __restrict__ ww_src, const int* __restrict__ ww_dst,
                                   const int* __restrict__ wwr_src, const int* __restrict__ wwr_dst,
                                   const int* __restrict__ wd_src, const int* __restrict__ wd_dst,
                                   const int* __restrict__ wdr_src, const int* __restrict__ wdr_dst) {
    const int total = 2 * E_WW + 2 * E_WD;
    for (int i = blockIdx.x * blockDim.x + threadIdx.x; i < total; i += gridDim.x * blockDim.x) {
        if (i < E_WW) {
            int p = atomicAdd(&g_cur_ww[ww_dst[i]], 1);  g_col_ww[p] = ww_src[i];
        } else if (i < 2 * E_WW) {
            int j = i - E_WW;
            int p = atomicAdd(&g_cur_wwr[wwr_dst[j]], 1); g_col_wwr[p] = wwr_src[j];
        } else if (i < 2 * E_WW + E_WD) {
            int j = i - 2 * E_WW;
            int p = atomicAdd(&g_cur_wd[wd_dst[j]], 1);   g_col_wd[p] = wd_src[j];
        } else {
            int j = i - 2 * E_WW - E_WD;
            int p = atomicAdd(&g_cur_wdr[wdr_dst[j]], 1); g_col_wdr[p] = wdr_src[j];
        }
    }
}

// ---------------- weight concat prep ----------------
__global__ void prep_w_kernel(const float* __restrict__ Ws, const float* __restrict__ Wn, int K) {
    int i = blockIdx.x * blockDim.x + threadIdx.x;
    if (i >= K * 128) return;
    int k = i / 128, n = i % 128;
    int KN = K * 128;
    g_Bw[k * 512 + n]       = Wn[0 * KN + k * 128 + n];
    g_Bw[k * 512 + 128 + n] = Wn[1 * KN + k * 128 + n];
    g_Bw[k * 512 + 256 + n] = Wn[2 * KN + k * 128 + n];
    g_Bw[k * 512 + 384 + n] = Ws[0 * KN + k * 128 + n] + Ws[1 * KN + k * 128 + n]
                            + Ws[3 * KN + k * 128 + n];
}
__global__ void prep_d_kernel(const float* __restrict__ Ws, const float* __restrict__ Wn, int K) {
    int i = blockIdx.x * blockDim.x + threadIdx.x;
    if (i >= K * 128) return;
    int k = i / 128, n = i % 128;
    int KN = K * 128;
    g_Bd[k * 256 + n]       = Wn[3 * KN + k * 128 + n];
    g_Bd[k * 256 + 128 + n] = Ws[2 * KN + k * 128 + n];
}

// ---------------- tf32 tensor-core GEMM: C[M,N] = A[M,K] @ B[K,N] ----------------
// Block tile 128x128, BK=16, 256 threads = 8 warps in 2(m) x 4(n); warp tile 64x32.
// Epilogue routes neighbor-segment columns to fp16 buffers, self columns to fp32.
#define BM 128
#define BN 128
#define BK 16
#define SMP 132

__device__ __forceinline__ uint32_t f2tf32(float f) {
    uint32_t u;
    asm("cvt.rna.tf32.f32 %0, %1;" : "=r"(u) : "f"(f));
    return u;
}

// c_sel: 0 -> word (fp16 cols [0,384), fp32 self [384,512))
//        1 -> doc  (fp16 cols [0,128), fp32 self [128,256))
__global__ __launch_bounds__(256) void gemm_tf32_kernel(const float* __restrict__ a_ext,
                                                        int a_sel, int b_sel, int c_sel,
                                                        int M, int K, int N) {
    const float* A = (a_sel == 0) ? a_ext : (a_sel == 1 ? (const float*)g_xw : (const float*)g_xd);
    const float* B = (b_sel == 0) ? (const float*)g_Bw : (const float*)g_Bd;

    __shared__ uint32_t As[BK][SMP];   // [k][m]
    __shared__ uint32_t Bs[BK][SMP];   // [k][n]

    const int tid = threadIdx.x;
    const int warp = tid >> 5, lane = tid & 31;
    const int g = lane >> 2, t = lane & 3;
    const int wm0 = (warp & 1) * 64;
    const int wn0 = (warp >> 1) * 32;
    const int row0 = blockIdx.y * BM, col0 = blockIdx.x * BN;

    float c[4][4][4];
    #pragma unroll
    for (int i = 0; i < 4; ++i)
        #pragma unroll
        for (int j = 0; j < 4; ++j)
            #pragma unroll
            for (int r = 0; r < 4; ++r) c[i][j][r] = 0.0f;

    const int ar = tid >> 2;
    const int ak = (tid & 3) * 4;
    const int br = tid >> 5;
    const int bc = (tid & 31) * 4;

    for (int k0 = 0; k0 < K; k0 += BK) {
        #pragma unroll
        for (int h = 0; h < 2; ++h) {
            int r = ar + h * 64;
            int gr = row0 + r;
            float4 v = make_float4(0.f, 0.f, 0.f, 0.f);
            if (gr < M) v = *reinterpret_cast<const float4*>(A + (size_t)gr * K + k0 + ak);
            As[ak + 0][r] = f2tf32(v.x);
            As[ak + 1][r] = f2tf32(v.y);
            As[ak + 2][r] = f2tf32(v.z);
            As[ak + 3][r] = f2tf32(v.w);
        }
        #pragma unroll
        for (int h = 0; h < 2; ++h) {
            int r = br + h * 8;
            float4 v = *reinterpret_cast<const float4*>(B + (size_t)(k0 + r) * N + col0 + bc);
            uint4 u;
            u.x = f2tf32(v.x); u.y = f2tf32(v.y); u.z = f2tf32(v.z); u.w = f2tf32(v.w);
            *reinterpret_cast<uint4*>(&Bs[r][bc]) = u;
        }
        __syncthreads();

        #pragma unroll
        for (int kk = 0; kk < BK; kk += 8) {
            uint32_t af[4][4], bf[4][2];
            #pragma unroll
            for (int i = 0; i < 4; ++i) {
                int r = wm0 + i * 16 + g;
                af[i][0] = As[kk + t][r];
                af[i][1] = As[kk + t][r + 8];
                af[i][2] = As[kk + t + 4][r];
                af[i][3] = As[kk + t + 4][r + 8];
            }
            #pragma unroll
            for (int j = 0; j < 4; ++j) {
                int cc = wn0 + j * 8 + g;
                bf[j][0] = Bs[kk + t][cc];
                bf[j][1] = Bs[kk + t + 4][cc];
            }
            #pragma unroll
            for (int i = 0; i < 4; ++i)
                #pragma unroll
                for (int j = 0; j < 4; ++j) {
                    asm volatile(
                        "mma.sync.aligned.m16n8k8.row.col.f32.tf32.tf32.f32 "
                        "{%0,%1,%2,%3}, {%4,%5,%6,%7}, {%8,%9}, {%0,%1,%2,%3};"
                        : "+f"(c[i][j][0]), "+f"(c[i][j][1]), "+f"(c[i][j][2]), "+f"(c[i][j][3])
                        : "r"(af[i][0]), "r"(af[i][1]), "r"(af[i][2]), "r"(af[i][3]),
                          "r"(bf[j][0]), "r"(bf[j][1]));
                }
        }
        __syncthreads();
    }

    // epilogue: split fp16 neighbor / fp32 self
    const int self0 = (c_sel == 0) ? 384 : 128;
    __half* HN = (c_sel == 0) ? g_twn : g_tdn;
    float*  FS = (c_sel == 0) ? g_tws : g_tds;
    const int hn_stride = self0;   // 384 for word, 128 for doc

    #pragma unroll
    for (int i = 0; i < 4; ++i) {
        #pragma unroll
        for (int hrow = 0; hrow < 2; ++hrow) {
            int r = row0 + wm0 + i * 16 + g + hrow * 8;
            if (r >= M) continue;
            #pragma unroll
            for (int j = 0; j < 4; ++j) {
                int cc = col0 + wn0 + j * 8 + 2 * t;
                float v0 = c[i][j][hrow * 2 + 0], v1 = c[i][j][hrow * 2 + 1];
                if (cc < self0) {
                    *reinterpret_cast<__half2*>(HN + (size_t)r * hn_stride + cc) =
                        __float22half2_rn(make_float2(v0, v1));
                } else {
                    *reinterpret_cast<float2*>(FS + (size_t)r * 128 + (cc - self0)) =
                        make_float2(v0, v1);
                }
            }
        }
    }
}

// ---------------- aggregation + combine (fp16 gather, fp32 accumulate) ----------------
__device__ __forceinline__ float4 gather_mean_h(const __half* __restrict__ t, int stride, int base,
                                                const int* __restrict__ ptr,
                                                const int* __restrict__ col, int v, int c4) {
    int beg = ptr[v], end = ptr[v + 1];
    float4 acc = make_float4(0.f, 0.f, 0.f, 0.f);
    for (int e = beg; e < end; ++e) {
        int s = col[e];
        const __half2* p = reinterpret_cast<const __half2*>(t + (size_t)s * stride + base + c4);
        float2 a = __half22float2(p[0]);
        float2 b = __half22float2(p[1]);
        acc.x += a.x; acc.y += a.y; acc.z += b.x; acc.w += b.y;
    }
    int d = end - beg;
    float inv = 1.0f / (float)(d > 0 ? d : 1);
    acc.x *= inv; acc.y *= inv; acc.z *= inv; acc.w *= inv;
    return acc;
}

template <bool FINAL>
__global__ void combine_word_kernel(const float* __restrict__ b,
                                    const float* __restrict__ lin_w,
                                    const float* __restrict__ lin_b,
                                    float* __restrict__ out) {
    int warp = (blockIdx.x * blockDim.x + threadIdx.x) >> 5;
    if (warp >= N_WORD) return;
    int lane = threadIdx.x & 31;
    int c4 = lane * 4;
    int v = warp;

    float4 h = *reinterpret_cast<const float4*>(g_tws + (size_t)v * 128 + c4); // self
    float4 m0 = gather_mean_h(g_twn, 384, 0,   g_ptr_ww,  g_col_ww,  v, c4);
    float4 m1 = gather_mean_h(g_twn, 384, 128, g_ptr_wwr, g_col_wwr, v, c4);
    float4 m3 = gather_mean_h(g_tdn, 128, 0,   g_ptr_wdr, g_col_wdr, v, c4);

    h.x = fmaxf(h.x + m0.x + m1.x + m3.x + b[c4 + 0] + b[128 + c4 + 0] + b[384 + c4 + 0], 0.f);
    h.y = fmaxf(h.y + m0.y + m1.y + m3.y + b[c4 + 1] + b[128 + c4 + 1] + b[384 + c4 + 1], 0.f);
    h.z = fmaxf(h.z + m0.z + m1.z + m3.z + b[c4 + 2] + b[128 + c4 + 2] + b[384 + c4 + 2], 0.f);
    h.w = fmaxf(h.w + m0.w + m1.w + m3.w + b[c4 + 3] + b[128 + c4 + 3] + b[384 + c4 + 3], 0.f);

    if (!FINAL) {
        *reinterpret_cast<float4*>(g_xw + (size_t)v * 128 + c4) = h;
    } else {
        float4 lw = *reinterpret_cast<const float4*>(lin_w + c4);
        float p = h.x * lw.x + h.y * lw.y + h.z * lw.z + h.w * lw.w;
        #pragma unroll
        for (int o = 16; o > 0; o >>= 1) p += __shfl_down_sync(0xffffffffu, p, o);
        if (lane == 0) out[v] = 1.0f / (1.0f + expf(-(p + lin_b[0])));
    }
}

template <bool FINAL>
__global__ void combine_doc_kernel(const float* __restrict__ b,
                                   const float* __restrict__ lin_w,
                                   const float* __restrict__ lin_b,
                                   float* __restrict__ out) {
    int warp = (blockIdx.x * blockDim.x + threadIdx.x) >> 5;
    if (warp >= N_DOC) return;
    int lane = threadIdx.x & 31;
    int c4 = lane * 4;
    int v = warp;

    float4 h = *reinterpret_cast<const float4*>(g_tds + (size_t)v * 128 + c4); // self
    float4 m2 = gather_mean_h(g_twn, 384, 256, g_ptr_wd, g_col_wd, v, c4);

    h.x = fmaxf(h.x + m2.x + b[256 + c4 + 0], 0.f);
    h.y = fmaxf(h.y + m2.y + b[256 + c4 + 1], 0.f);
    h.z = fmaxf(h.z + m2.z + b[256 + c4 + 2], 0.f);
    h.w = fmaxf(h.w + m2.w + b[256 + c4 + 3], 0.f);

    if (!FINAL) {
        *reinterpret_cast<float4*>(g_xd + (size_t)v * 128 + c4) = h;
    } else {
        float4 lw = *reinterpret_cast<const float4*>(lin_w + c4);
        float p = h.x * lw.x + h.y * lw.y + h.z * lw.z + h.w * lw.w;
        #pragma unroll
        for (int o = 16; o > 0; o >>= 1) p += __shfl_down_sync(0xffffffffu, p, o);
        if (lane == 0) out[N_WORD + v] = 1.0f / (1.0f + expf(-(p + lin_b[0])));
    }
}

// ---------------- host launch ----------------
extern "C" void kernel_launch(void* const* d_in, const int* in_sizes, int n_in,
                              void* d_out, int out_size) {
    const float* x_word  = (const float*)d_in[0];
    const float* x_doc   = (const float*)d_in[1];
    const int*   ww_src  = (const int*)d_in[2];
    const int*   ww_dst  = (const int*)d_in[3];
    const int*   wwr_src = (const int*)d_in[4];
    const int*   wwr_dst = (const int*)d_in[5];
    const int*   wd_src  = (const int*)d_in[6];
    const int*   wd_dst  = (const int*)d_in[7];
    const int*   wdr_src = (const int*)d_in[8];
    const int*   wdr_dst = (const int*)d_in[9];
    const float* Wself1  = (const float*)d_in[10];
    const float* Wneigh1 = (const float*)d_in[11];
    const float* b1      = (const float*)d_in[12];
    const float* Wself2  = (const float*)d_in[13];
    const float* Wneigh2 = (const float*)d_in[14];
    const float* b2      = (const float*)d_in[15];
    const float* lin_w   = (const float*)d_in[16];
    const float* lin_b   = (const float*)d_in[17];
    float* out = (float*)d_out;

    // --- CSR build (int atomics only) ---
    zero_cnt_kernel<<<(N_WORD + 256) / 256, 256>>>();
    hist_all_kernel<<<1184, 256>>>(ww_dst, wwr_dst, wd_dst, wdr_dst);
    scan_all_kernel<<<4, 1024>>>();
    scatter_all_kernel<<<1184, 256>>>(ww_src, ww_dst, wwr_src, wwr_dst,
                                      wd_src, wd_dst, wdr_src, wdr_dst);

    // --- layer 1 (K = 256) ---
    prep_w_kernel<<<(256 * 128 + 255) / 256, 256>>>(Wself1, Wneigh1, 256);
    prep_d_kernel<<<(256 * 128 + 255) / 256, 256>>>(Wself1, Wneigh1, 256);
    gemm_tf32_kernel<<<dim3(512 / BN, (N_WORD + BM - 1) / BM), 256>>>(x_word, 0, 0, 0, N_WORD, 256, 512);
    gemm_tf32_kernel<<<dim3(256 / BN, (N_DOC + BM - 1) / BM), 256>>>(x_doc, 0, 1, 1, N_DOC, 256, 256);
    combine_word_kernel<false><<<(N_WORD + 7) / 8, 256>>>(b1, lin_w, lin_b, out);
    combine_doc_kernel<false><<<(N_DOC + 7) / 8, 256>>>(b1, lin_w, lin_b, out);

    // --- layer 2 (K = 128) + fused final linear/sigmoid ---
    prep_w_kernel<<<(128 * 128 + 255) / 256, 256>>>(Wself2, Wneigh2, 128);
    prep_d_kernel<<<(128 * 128 + 255) / 256, 256>>>(Wself2, Wneigh2, 128);
    gemm_tf32_kernel<<<dim3(512 / BN, (N_WORD + BM - 1) / BM), 256>>>(nullptr, 1, 0, 0, N_WORD, 128, 512);
    gemm_tf32_kernel<<<dim3(256 / BN, (N_DOC + BM - 1) / BM), 256>>>(nullptr, 2, 1, 1, N_DOC, 128, 256);
    combine_word_kernel<true><<<(N_WORD + 7) / 8, 256>>>(b2, lin_w, lin_b, out);
    combine_doc_kernel<true><<<(N_DOC + 7) / 8, 256>>>(b2, lin_w, lin_b, out);
}

// round 6
// speedup vs baseline: 1.6781x; 1.0427x over previous
#include <cuda_runtime.h>
#include <cuda_fp16.h>
#include <math.h>
#include <stdint.h>

#define N_WORD 50000
#define N_DOC  10000
#define E_WW   800000
#define E_WD   320000

// ---------------- device scratch (static allocation only) ----------------
__device__ __half g_twn[(size_t)N_WORD * 384];  // [t_ww | t_wwr | t_wd] per word
__device__ float  g_tws[(size_t)N_WORD * 128];  // combined self transform (word)
__device__ __half g_tdn[(size_t)N_DOC * 128];   // t_wdr per doc
__device__ float  g_tds[(size_t)N_DOC * 128];   // self transform (doc)
__device__ float  g_xw[(size_t)N_WORD * 128];   // layer-1 word output
__device__ float  g_xd[(size_t)N_DOC * 128];    // layer-1 doc output
__device__ float  g_Bw[256 * 512];              // concat word weights
__device__ float  g_Bd[256 * 256];              // concat doc weights

// CSR per relation: 0=ww, 1=wwr, 2=wd(dst=doc), 3=wdr
__device__ int g_ptr_ww[N_WORD + 1], g_ptr_wwr[N_WORD + 1], g_ptr_wdr[N_WORD + 1];
__device__ int g_ptr_wd[N_DOC + 1];
__device__ int g_cur_ww[N_WORD + 1], g_cur_wwr[N_WORD + 1], g_cur_wdr[N_WORD + 1];
__device__ int g_cur_wd[N_DOC + 1];
__device__ int g_col_ww[E_WW], g_col_wwr[E_WW], g_col_wd[E_WD], g_col_wdr[E_WD];

__device__ __forceinline__ int* cur_of(int rel) {
    switch (rel) { case 0: return g_cur_ww; case 1: return g_cur_wwr;
                   case 2: return g_cur_wd; default: return g_cur_wdr; }
}
__device__ __forceinline__ int* ptr_of(int rel) {
    switch (rel) { case 0: return g_ptr_ww; case 1: return g_ptr_wwr;
                   case 2: return g_ptr_wd; default: return g_ptr_wdr; }
}

// ---------------- CSR build ----------------
__global__ void zero_cnt_kernel() {
    int i = blockIdx.x * blockDim.x + threadIdx.x;
    if (i < N_WORD + 1) { g_cur_ww[i] = 0; g_cur_wwr[i] = 0; g_cur_wdr[i] = 0; }
    if (i < N_DOC + 1)  { g_cur_wd[i] = 0; }
}

__global__ void hist_all_kernel(const int* __restrict__ ww_dst, const int* __restrict__ wwr_dst,
                                const int* __restrict__ wd_dst, const int* __restrict__ wdr_dst) {
    const int total = 2 * E_WW + 2 * E_WD;
    for (int i = blockIdx.x * blockDim.x + threadIdx.x; i < total; i += gridDim.x * blockDim.x) {
        if (i < E_WW)                  atomicAdd(&g_cur_ww[ww_dst[i]], 1);
        else if (i < 2 * E_WW)         atomicAdd(&g_cur_wwr[wwr_dst[i - E_WW]], 1);
        else if (i < 2 * E_WW + E_WD)  atomicAdd(&g_cur_wd[wd_dst[i - 2 * E_WW]], 1);
        else                           atomicAdd(&g_cur_wdr[wdr_dst[i - 2 * E_WW - E_WD]], 1);
    }
}

__global__ void scan_all_kernel() {
    int rel = blockIdx.x;
    int n = (rel == 2) ? N_DOC : N_WORD;
    int* cnt = cur_of(rel);
    int* ptr = ptr_of(rel);
    __shared__ int sh_warp[32];
    __shared__ int sh_carry;
    if (threadIdx.x == 0) sh_carry = 0;
    __syncthreads();
    for (int base = 0; base < n; base += 1024) {
        int i = base + (int)threadIdx.x;
        int v = (i < n) ? cnt[i] : 0;
        int lane = threadIdx.x & 31, wid = threadIdx.x >> 5;
        int x = v;
        #pragma unroll
        for (int o = 1; o < 32; o <<= 1) { int y = __shfl_up_sync(0xffffffffu, x, o); if (lane >= o) x += y; }
        if (lane == 31) sh_warp[wid] = x;
        __syncthreads();
        if (wid == 0) {
            int s = sh_warp[lane];
            #pragma unroll
            for (int o = 1; o < 32; o <<= 1) { int y = __shfl_up_sync(0xffffffffu, s, o); if (lane >= o) s += y; }
            sh_warp[lane] = s;
        }
        __syncthreads();
        int pre = (wid > 0) ? sh_warp[wid - 1] : 0;
        int incl = x + pre + sh_carry;
        if (i < n) { int excl = incl - v; ptr[i] = excl; cnt[i] = excl; }
        __syncthreads();
        if (threadIdx.x == 1023) sh_carry = incl;
        __syncthreads();
    }
    if (threadIdx.x == 0) { ptr[n] = sh_carry; cnt[n] = sh_carry; }
}

__global__ void scatter_all_kernel(const int* __restrict__ ww_src, const int* __restrict__ ww_dst,
                                   const int* __restrict__ wwr_src, const int* __restrict__ wwr_dst,
                                   const int* __restrict__ wd_src, const int* __restrict__ wd_dst,
                                   const int* __restrict__ wdr_src, const int* __restrict__ wdr_dst) {
    const int total = 2 * E_WW + 2 * E_WD;
    for (int i = blockIdx.x * blockDim.x + threadIdx.x; i < total; i += gridDim.x * blockDim.x) {
        if (i < E_WW) {
            int p = atomicAdd(&g_cur_ww[ww_dst[i]], 1);  g_col_ww[p] = ww_src[i];
        } else if (i < 2 * E_WW) {
            int j = i - E_WW;
            int p = atomicAdd(&g_cur_wwr[wwr_dst[j]], 1); g_col_wwr[p] = wwr_src[j];
        } else if (i < 2 * E_WW + E_WD) {
            int j = i - 2 * E_WW;
            int p = atomicAdd(&g_cur_wd[wd_dst[j]], 1);   g_col_wd[p] = wd_src[j];
        } else {
            int j = i - 2 * E_WW - E_WD;
            int p = atomicAdd(&g_cur_wdr[wdr_dst[j]], 1); g_col_wdr[p] = wdr_src[j];
        }
    }
}

// ---------------- weight concat prep ----------------
__global__ void prep_w_kernel(const float* __restrict__ Ws, const float* __restrict__ Wn, int K) {
    int i = blockIdx.x * blockDim.x + threadIdx.x;
    if (i >= K * 128) return;
    int k = i / 128, n = i % 128;
    int KN = K * 128;
    g_Bw[k * 512 + n]       = Wn[0 * KN + k * 128 + n];
    g_Bw[k * 512 + 128 + n] = Wn[1 * KN + k * 128 + n];
    g_Bw[k * 512 + 256 + n] = Wn[2 * KN + k * 128 + n];
    g_Bw[k * 512 + 384 + n] = Ws[0 * KN + k * 128 + n] + Ws[1 * KN + k * 128 + n]
                            + Ws[3 * KN + k * 128 + n];
}
__global__ void prep_d_kernel(const float* __restrict__ Ws, const float* __restrict__ Wn, int K) {
    int i = blockIdx.x * blockDim.x + threadIdx.x;
    if (i >= K * 128) return;
    int k = i / 128, n = i % 128;
    int KN = K * 128;
    g_Bd[k * 256 + n]       = Wn[3 * KN + k * 128 + n];
    g_Bd[k * 256 + 128 + n] = Ws[2 * KN + k * 128 + n];
}

// ---------------- tf32 tensor-core GEMM ----------------
#define BM 128
#define BN 128
#define BK 16
#define SMP 132

__device__ __forceinline__ uint32_t f2tf32(float f) {
    uint32_t u;
    asm("cvt.rna.tf32.f32 %0, %1;" : "=r"(u) : "f"(f));
    return u;
}

__global__ __launch_bounds__(256) void gemm_tf32_kernel(const float* __restrict__ a_ext,
                                                        int a_sel, int b_sel, int c_sel,
                                                        int M, int K, int N) {
    const float* A = (a_sel == 0) ? a_ext : (a_sel == 1 ? (const float*)g_xw : (const float*)g_xd);
    const float* B = (b_sel == 0) ? (const float*)g_Bw : (const float*)g_Bd;

    __shared__ uint32_t As[BK][SMP];
    __shared__ uint32_t Bs[BK][SMP];

    const int tid = threadIdx.x;
    const int warp = tid >> 5, lane = tid & 31;
    const int g = lane >> 2, t = lane & 3;
    const int wm0 = (warp & 1) * 64;
    const int wn0 = (warp >> 1) * 32;
    const int row0 = blockIdx.y * BM, col0 = blockIdx.x * BN;

    float c[4][4][4];
    #pragma unroll
    for (int i = 0; i < 4; ++i)
        #pragma unroll
        for (int j = 0; j < 4; ++j)
            #pragma unroll
            for (int r = 0; r < 4; ++r) c[i][j][r] = 0.0f;

    const int ar = tid >> 2;
    const int ak = (tid & 3) * 4;
    const int br = tid >> 5;
    const int bc = (tid & 31) * 4;

    for (int k0 = 0; k0 < K; k0 += BK) {
        #pragma unroll
        for (int h = 0; h < 2; ++h) {
            int r = ar + h * 64;
            int gr = row0 + r;
            float4 v = make_float4(0.f, 0.f, 0.f, 0.f);
            if (gr < M) v = *reinterpret_cast<const float4*>(A + (size_t)gr * K + k0 + ak);
            As[ak + 0][r] = f2tf32(v.x);
            As[ak + 1][r] = f2tf32(v.y);
            As[ak + 2][r] = f2tf32(v.z);
            As[ak + 3][r] = f2tf32(v.w);
        }
        #pragma unroll
        for (int h = 0; h < 2; ++h) {
            int r = br + h * 8;
            float4 v = *reinterpret_cast<const float4*>(B + (size_t)(k0 + r) * N + col0 + bc);
            uint4 u;
            u.x = f2tf32(v.x); u.y = f2tf32(v.y); u.z = f2tf32(v.z); u.w = f2tf32(v.w);
            *reinterpret_cast<uint4*>(&Bs[r][bc]) = u;
        }
        __syncthreads();

        #pragma unroll
        for (int kk = 0; kk < BK; kk += 8) {
            uint32_t af[4][4], bf[4][2];
            #pragma unroll
            for (int i = 0; i < 4; ++i) {
                int r = wm0 + i * 16 + g;
                af[i][0] = As[kk + t][r];
                af[i][1] = As[kk + t][r + 8];
                af[i][2] = As[kk + t + 4][r];
                af[i][3] = As[kk + t + 4][r + 8];
            }
            #pragma unroll
            for (int j = 0; j < 4; ++j) {
                int cc = wn0 + j * 8 + g;
                bf[j][0] = Bs[kk + t][cc];
                bf[j][1] = Bs[kk + t + 4][cc];
            }
            #pragma unroll
            for (int i = 0; i < 4; ++i)
                #pragma unroll
                for (int j = 0; j < 4; ++j) {
                    asm volatile(
                        "mma.sync.aligned.m16n8k8.row.col.f32.tf32.tf32.f32 "
                        "{%0,%1,%2,%3}, {%4,%5,%6,%7}, {%8,%9}, {%0,%1,%2,%3};"
                        : "+f"(c[i][j][0]), "+f"(c[i][j][1]), "+f"(c[i][j][2]), "+f"(c[i][j][3])
                        : "r"(af[i][0]), "r"(af[i][1]), "r"(af[i][2]), "r"(af[i][3]),
                          "r"(bf[j][0]), "r"(bf[j][1]));
                }
        }
        __syncthreads();
    }

    const int self0 = (c_sel == 0) ? 384 : 128;
    __half* HN = (c_sel == 0) ? g_twn : g_tdn;
    float*  FS = (c_sel == 0) ? g_tws : g_tds;
    const int hn_stride = self0;

    #pragma unroll
    for (int i = 0; i < 4; ++i) {
        #pragma unroll
        for (int hrow = 0; hrow < 2; ++hrow) {
            int r = row0 + wm0 + i * 16 + g + hrow * 8;
            if (r >= M) continue;
            #pragma unroll
            for (int j = 0; j < 4; ++j) {
                int cc = col0 + wn0 + j * 8 + 2 * t;
                float v0 = c[i][j][hrow * 2 + 0], v1 = c[i][j][hrow * 2 + 1];
                if (cc < self0) {
                    *reinterpret_cast<__half2*>(HN + (size_t)r * hn_stride + cc) =
                        __float22half2_rn(make_float2(v0, v1));
                } else {
                    *reinterpret_cast<float2*>(FS + (size_t)r * 128 + (cc - self0)) =
                        make_float2(v0, v1);
                }
            }
        }
    }
}

// ---------------- aggregation + combine (4-deep ILP gather) ----------------
__device__ __forceinline__ void acc_h4(float4& acc, const __half* __restrict__ p) {
    const __half2* q = reinterpret_cast<const __half2*>(p);
    float2 a = __half22float2(q[0]);
    float2 b = __half22float2(q[1]);
    acc.x += a.x; acc.y += a.y; acc.z += b.x; acc.w += b.y;
}

__device__ __forceinline__ float4 gather_mean_h(const __half* __restrict__ t, int stride, int base,
                                                const int* __restrict__ ptr,
                                                const int* __restrict__ col, int v, int c4) {
    int beg = ptr[v], end = ptr[v + 1];
    float4 a0 = make_float4(0.f, 0.f, 0.f, 0.f);
    float4 a1 = make_float4(0.f, 0.f, 0.f, 0.f);
    float4 a2 = make_float4(0.f, 0.f, 0.f, 0.f);
    float4 a3 = make_float4(0.f, 0.f, 0.f, 0.f);
    int e = beg;
    for (; e + 4 <= end; e += 4) {
        int s0 = col[e], s1 = col[e + 1], s2 = col[e + 2], s3 = col[e + 3];
        const __half* p0 = t + (size_t)s0 * stride + base + c4;
        const __half* p1 = t + (size_t)s1 * stride + base + c4;
        const __half* p2 = t + (size_t)s2 * stride + base + c4;
        const __half* p3 = t + (size_t)s3 * stride + base + c4;
        acc_h4(a0, p0); acc_h4(a1, p1); acc_h4(a2, p2); acc_h4(a3, p3);
    }
    for (; e < end; ++e) {
        int s = col[e];
        acc_h4(a0, t + (size_t)s * stride + base + c4);
    }
    a0.x += a1.x + a2.x + a3.x;
    a0.y += a1.y + a2.y + a3.y;
    a0.z += a1.z + a2.z + a3.z;
    a0.w += a1.w + a2.w + a3.w;
    int d = end - beg;
    float inv = 1.0f / (float)(d > 0 ? d : 1);
    a0.x *= inv; a0.y *= inv; a0.z *= inv; a0.w *= inv;
    return a0;
}

template <bool FINAL>
__global__ void combine_word_kernel(const float* __restrict__ b,
                                    const float* __restrict__ lin_w,
                                    const float* __restrict__ lin_b,
                                    float* __restrict__ out) {
    int warp = (blockIdx.x * blockDim.x + threadIdx.x) >> 5;
    if (warp >= N_WORD) return;
    int lane = threadIdx.x & 31;
    int c4 = lane * 4;
    int v = warp;

    float4 h = *reinterpret_cast<const float4*>(g_tws + (size_t)v * 128 + c4);
    float4 m0 = gather_mean_h(g_twn, 384, 0,   g_ptr_ww,  g_col_ww,  v, c4);
    float4 m1 = gather_mean_h(g_twn, 384, 128, g_ptr_wwr, g_col_wwr, v, c4);
    float4 m3 = gather_mean_h(g_tdn, 128, 0,   g_ptr_wdr, g_col_wdr, v, c4);

    h.x = fmaxf(h.x + m0.x + m1.x + m3.x + b[c4 + 0] + b[128 + c4 + 0] + b[384 + c4 + 0], 0.f);
    h.y = fmaxf(h.y + m0.y + m1.y + m3.y + b[c4 + 1] + b[128 + c4 + 1] + b[384 + c4 + 1], 0.f);
    h.z = fmaxf(h.z + m0.z + m1.z + m3.z + b[c4 + 2] + b[128 + c4 + 2] + b[384 + c4 + 2], 0.f);
    h.w = fmaxf(h.w + m0.w + m1.w + m3.w + b[c4 + 3] + b[128 + c4 + 3] + b[384 + c4 + 3], 0.f);

    if (!FINAL) {
        *reinterpret_cast<float4*>(g_xw + (size_t)v * 128 + c4) = h;
    } else {
        float4 lw = *reinterpret_cast<const float4*>(lin_w + c4);
        float p = h.x * lw.x + h.y * lw.y + h.z * lw.z + h.w * lw.w;
        #pragma unroll
        for (int o = 16; o > 0; o >>= 1) p += __shfl_down_sync(0xffffffffu, p, o);
        if (lane == 0) out[v] = 1.0f / (1.0f + expf(-(p + lin_b[0])));
    }
}

template <bool FINAL>
__global__ void combine_doc_kernel(const float* __restrict__ b,
                                   const float* __restrict__ lin_w,
                                   const float* __restrict__ lin_b,
                                   float* __restrict__ out) {
    int warp = (blockIdx.x * blockDim.x + threadIdx.x) >> 5;
    if (warp >= N_DOC) return;
    int lane = threadIdx.x & 31;
    int c4 = lane * 4;
    int v = warp;

    float4 h = *reinterpret_cast<const float4*>(g_tds + (size_t)v * 128 + c4);
    float4 m2 = gather_mean_h(g_twn, 384, 256, g_ptr_wd, g_col_wd, v, c4);

    h.x = fmaxf(h.x + m2.x + b[256 + c4 + 0], 0.f);
    h.y = fmaxf(h.y + m2.y + b[256 + c4 + 1], 0.f);
    h.z = fmaxf(h.z + m2.z + b[256 + c4 + 2], 0.f);
    h.w = fmaxf(h.w + m2.w + b[256 + c4 + 3], 0.f);

    if (!FINAL) {
        *reinterpret_cast<float4*>(g_xd + (size_t)v * 128 + c4) = h;
    } else {
        float4 lw = *reinterpret_cast<const float4*>(lin_w + c4);
        float p = h.x * lw.x + h.y * lw.y + h.z * lw.z + h.w * lw.w;
        #pragma unroll
        for (int o = 16; o > 0; o >>= 1) p += __shfl_down_sync(0xffffffffu, p, o);
        if (lane == 0) out[N_WORD + v] = 1.0f / (1.0f + expf(-(p + lin_b[0])));
    }
}

// ---------------- host launch ----------------
extern "C" void kernel_launch(void* const* d_in, const int* in_sizes, int n_in,
                              void* d_out, int out_size) {
    const float* x_word  = (const float*)d_in[0];
    const float* x_doc   = (const float*)d_in[1];
    const int*   ww_src  = (const int*)d_in[2];
    const int*   ww_dst  = (const int*)d_in[3];
    const int*   wwr_src = (const int*)d_in[4];
    const int*   wwr_dst = (const int*)d_in[5];
    const int*   wd_src  = (const int*)d_in[6];
    const int*   wd_dst  = (const int*)d_in[7];
    const int*   wdr_src = (const int*)d_in[8];
    const int*   wdr_dst = (const int*)d_in[9];
    const float* Wself1  = (const float*)d_in[10];
    const float* Wneigh1 = (const float*)d_in[11];
    const float* b1      = (const float*)d_in[12];
    const float* Wself2  = (const float*)d_in[13];
    const float* Wneigh2 = (const float*)d_in[14];
    const float* b2      = (const float*)d_in[15];
    const float* lin_w   = (const float*)d_in[16];
    const float* lin_b   = (const float*)d_in[17];
    float* out = (float*)d_out;

    // lazy-init side stream + fork/join events (host-side objects only)
    static cudaStream_t s_csr = nullptr;
    static cudaEvent_t ev_fork = nullptr, ev_join = nullptr;
    if (s_csr == nullptr) {
        cudaStreamCreateWithFlags(&s_csr, cudaStreamNonBlocking);
        cudaEventCreateWithFlags(&ev_fork, cudaEventDisableTiming);
        cudaEventCreateWithFlags(&ev_join, cudaEventDisableTiming);
    }

    // fork: CSR build runs on s_csr concurrently with layer-1 GEMMs on stream 0
    cudaEventRecord(ev_fork, 0);
    cudaStreamWaitEvent(s_csr, ev_fork, 0);

    zero_cnt_kernel<<<(N_WORD + 256) / 256, 256, 0, s_csr>>>();
    hist_all_kernel<<<1184, 256, 0, s_csr>>>(ww_dst, wwr_dst, wd_dst, wdr_dst);
    scan_all_kernel<<<4, 1024, 0, s_csr>>>();
    scatter_all_kernel<<<1184, 256, 0, s_csr>>>(ww_src, ww_dst, wwr_src, wwr_dst,
                                                wd_src, wd_dst, wdr_src, wdr_dst);
    cudaEventRecord(ev_join, s_csr);

    // --- layer 1 (K = 256), independent of CSR build ---
    prep_w_kernel<<<(256 * 128 + 255) / 256, 256>>>(Wself1, Wneigh1, 256);
    prep_d_kernel<<<(256 * 128 + 255) / 256, 256>>>(Wself1, Wneigh1, 256);
    gemm_tf32_kernel<<<dim3(512 / BN, (N_WORD + BM - 1) / BM), 256>>>(x_word, 0, 0, 0, N_WORD, 256, 512);
    gemm_tf32_kernel<<<dim3(256 / BN, (N_DOC + BM - 1) / BM), 256>>>(x_doc, 0, 1, 1, N_DOC, 256, 256);

    // join: combines need both GEMM outputs and the CSR
    cudaStreamWaitEvent(0, ev_join, 0);
    combine_word_kernel<false><<<(N_WORD + 7) / 8, 256>>>(b1, lin_w, lin_b, out);
    combine_doc_kernel<false><<<(N_DOC + 7) / 8, 256>>>(b1, lin_w, lin_b, out);

    // --- layer 2 (K = 128) + fused final linear/sigmoid ---
    prep_w_kernel<<<(128 * 128 + 255) / 256, 256>>>(Wself2, Wneigh2, 128);
    prep_d_kernel<<<(128 * 128 + 255) / 256, 256>>>(Wself2, Wneigh2, 128);
    gemm_tf32_kernel<<<dim3(512 / BN, (N_WORD + BM - 1) / BM), 256>>>(nullptr, 1, 0, 0, N_WORD, 128, 512);
    gemm_tf32_kernel<<<dim3(256 / BN, (N_DOC + BM - 1) / BM), 256>>>(nullptr, 2, 1, 1, N_DOC, 128, 256);
    combine_word_kernel<true><<<(N_WORD + 7) / 8, 256>>>(b2, lin_w, lin_b, out);
    combine_doc_kernel<true><<<(N_DOC + 7) / 8, 256>>>(b2, lin_w, lin_b, out);
}